// round 10
// baseline (speedup 1.0000x reference)
#include <cuda_runtime.h>
#include <cuda_fp16.h>
#include <math.h>
#include <stdint.h>

#define BATCH 8192
#define PIX 784
#define WIRES 10
#define DIM 1024
#define QDEPTH 20
#define NGATES (QDEPTH * WIRES)   // 200

#define KBIG 1024                 // pure fp16: A=fp16(S), B=fp16(U)
#define NBIG 1664                 // 832 j-slots x (re,im) interleaved
#define BKT  64                   // K per smem tile
#define NKT  (KBIG / BKT)         // 16

// ---------------- scratch ----------------
__device__ float2 g_gates[NGATES * 4];
__device__ __half g_As[(size_t)BATCH * KBIG];   // A' [m][k]
__device__ __half g_Bb[(size_t)KBIG * NBIG];    // B' [k][n]  (n = 2j | 2j+1 -> re|im)

// ---------------- helpers ----------------
__device__ __forceinline__ uint32_t smem_u32(const void* p) {
    uint32_t a;
    asm("{ .reg .u64 t; cvta.to.shared.u64 t, %1; cvt.u32.u64 %0, t; }" : "=r"(a) : "l"(p));
    return a;
}
__device__ __forceinline__ void cp_async16(uint32_t dst, const void* src) {
    asm volatile("cp.async.cg.shared.global [%0], [%1], 16;" :: "r"(dst), "l"(src));
}
#define CP_COMMIT() asm volatile("cp.async.commit_group;" ::: "memory")
#define CP_WAIT2()  asm volatile("cp.async.wait_group 2;" ::: "memory")

__device__ __forceinline__ void ldsm_x4(uint32_t* r, uint32_t addr) {
    asm volatile("ldmatrix.sync.aligned.m8n8.x4.shared.b16 {%0,%1,%2,%3}, [%4];"
                 : "=r"(r[0]), "=r"(r[1]), "=r"(r[2]), "=r"(r[3]) : "r"(addr));
}
__device__ __forceinline__ void ldsm_x4_t(uint32_t* r, uint32_t addr) {
    asm volatile("ldmatrix.sync.aligned.m8n8.x4.trans.shared.b16 {%0,%1,%2,%3}, [%4];"
                 : "=r"(r[0]), "=r"(r[1]), "=r"(r[2]), "=r"(r[3]) : "r"(addr));
}
__device__ __forceinline__ void mma16816(float* d, const uint32_t* a, const uint32_t* b) {
    asm volatile(
        "mma.sync.aligned.m16n8k16.row.col.f32.f16.f16.f32 "
        "{%0,%1,%2,%3}, {%4,%5,%6,%7}, {%8,%9}, {%0,%1,%2,%3};"
        : "+f"(d[0]), "+f"(d[1]), "+f"(d[2]), "+f"(d[3])
        : "r"(a[0]), "r"(a[1]), "r"(a[2]), "r"(a[3]), "r"(b[0]), "r"(b[1]));
}
__device__ __forceinline__ float2 cmul(float2 g, float2 v) {
    return make_float2(g.x * v.x - g.y * v.y, g.x * v.y + g.y * v.x);
}
__device__ __forceinline__ float2 cadd(float2 a, float2 b) {
    return make_float2(a.x + b.x, a.y + b.y);
}

// ---------------- kernel 1: Rot gates ----------------
__global__ void k_gates(const float* __restrict__ qw) {
    int g = blockIdx.x * blockDim.x + threadIdx.x;
    if (g >= NGATES) return;
    float phi = qw[g * 3 + 0], th = qw[g * 3 + 1], om = qw[g * 3 + 2];
    float c = cosf(0.5f * th), s = sinf(0.5f * th);
    float A = 0.5f * (phi + om), B = 0.5f * (phi - om);
    float cA = cosf(A), sA = sinf(A), cB = cosf(B), sB = sinf(B);
    g_gates[g * 4 + 0] = make_float2(cA * c, -sA * c);
    g_gates[g * 4 + 1] = make_float2(-cB * s, -sB * s);
    g_gates[g * 4 + 2] = make_float2(cB * s, -sB * s);
    g_gates[g * 4 + 3] = make_float2(cA * c,  sA * c);
}

// ---------------- kernel 2: fused angles + fp16 product state ----------------
__global__ __launch_bounds__(256) void k_angA(const float* __restrict__ x,
                                              const float* __restrict__ W,
                                              const float* __restrict__ bias) {
    const int warp = blockIdx.x * 8 + (threadIdx.x >> 5);
    const int lane = threadIdx.x & 31;
    const float* xr = x + (size_t)warp * PIX;
    float acc[WIRES];
#pragma unroll
    for (int w = 0; w < WIRES; w++) acc[w] = 0.f;
    for (int p = lane; p < PIX; p += 32) {
        float xv = xr[p];
#pragma unroll
        for (int w = 0; w < WIRES; w++)
            acc[w] = fmaf(xv, __ldg(&W[w * PIX + p]), acc[w]);
    }
#pragma unroll
    for (int w = 0; w < WIRES; w++) {
#pragma unroll
        for (int o = 16; o; o >>= 1)
            acc[w] += __shfl_xor_sync(0xffffffffu, acc[w], o);
    }
    float cl = 1.f, cr = 1.f;
#pragma unroll
    for (int w = 0; w < 5; w++) {
        float h = 0.5f * (acc[w] + __ldg(&bias[w]));
        float s, c; sincosf(h, &s, &c);
        cl *= ((lane >> (4 - w)) & 1) ? s : c;
    }
#pragma unroll
    for (int w = 5; w < 10; w++) {
        float h = 0.5f * (acc[w] + __ldg(&bias[w]));
        float s, c; sincosf(h, &s, &c);
        cr *= ((lane >> (9 - w)) & 1) ? s : c;
    }
    char* rowb = (char*)(g_As + (size_t)warp * KBIG) + lane * 64;
#pragma unroll
    for (int q = 0; q < 32; q += 8) {
        uint32_t u[4];
#pragma unroll
        for (int j = 0; j < 4; j++) {
            float r0 = __shfl_sync(0xffffffffu, cr, q + 2 * j);
            float r1 = __shfl_sync(0xffffffffu, cr, q + 2 * j + 1);
            __half2 h2 = __floats2half2_rn(cl * r0, cl * r1);
            u[j] = *(uint32_t*)&h2;
        }
        *(uint4*)(rowb + q * 2) = make_uint4(u[0], u[1], u[2], u[3]);
    }
}

// ---------------- kernel 3: build U, register state, writes B' directly ------
__global__ __launch_bounds__(512) void k_buildU() {
    __shared__ float4 buf[2][512];
    __shared__ float2 gs[NGATES * 4];
    const int t = threadIdx.x;
    const int lane = t & 31;
    const int col = blockIdx.x;

    for (int i = t; i < NGATES * 4; i += 512) gs[i] = g_gates[i];
    float2 a0 = make_float2(t == col ? 1.f : 0.f, 0.f);
    float2 a1 = make_float2((t + 512) == col ? 1.f : 0.f, 0.f);
    __syncthreads();

    int pb = 0;
    for (int l = 0; l < QDEPTH; l++) {
        // wire 0 (bit 9): thread-local pair
        {
            const int gi = (l * WIRES + 0) * 4;
            const float2 g00 = gs[gi], g01 = gs[gi + 1], g10 = gs[gi + 2], g11 = gs[gi + 3];
            float2 n0 = cadd(cmul(g00, a0), cmul(g01, a1));
            float2 n1 = cadd(cmul(g10, a0), cmul(g11, a1));
            a0 = n0; a1 = n1;
        }
        // wires 1..4 (bits 8..5): smem exchange
#pragma unroll
        for (int w = 1; w <= 4; w++) {
            const int gi = (l * WIRES + w) * 4;
            const float2 g00 = gs[gi], g01 = gs[gi + 1], g10 = gs[gi + 2], g11 = gs[gi + 3];
            const int b = 9 - w;
            const int d = 1 << b;
            buf[pb][t] = make_float4(a0.x, a0.y, a1.x, a1.y);
            __syncthreads();
            float4 p4 = buf[pb][t ^ d];
            pb ^= 1;
            float2 p0 = make_float2(p4.x, p4.y), p1 = make_float2(p4.z, p4.w);
            if ((t >> b) & 1) {
                a0 = cadd(cmul(g10, p0), cmul(g11, a0));
                a1 = cadd(cmul(g10, p1), cmul(g11, a1));
            } else {
                a0 = cadd(cmul(g00, a0), cmul(g01, p0));
                a1 = cadd(cmul(g00, a1), cmul(g01, p1));
            }
        }
        // wires 5..9 (bits 4..0): shfl
#pragma unroll
        for (int w = 5; w <= 9; w++) {
            const int gi = (l * WIRES + w) * 4;
            const float2 g00 = gs[gi], g01 = gs[gi + 1], g10 = gs[gi + 2], g11 = gs[gi + 3];
            const int b = 9 - w;
            const int d = 1 << b;
            float2 p0, p1;
            p0.x = __shfl_xor_sync(0xffffffffu, a0.x, d);
            p0.y = __shfl_xor_sync(0xffffffffu, a0.y, d);
            p1.x = __shfl_xor_sync(0xffffffffu, a1.x, d);
            p1.y = __shfl_xor_sync(0xffffffffu, a1.y, d);
            if ((lane >> b) & 1) {
                a0 = cadd(cmul(g10, p0), cmul(g11, a0));
                a1 = cadd(cmul(g10, p1), cmul(g11, a1));
            } else {
                a0 = cadd(cmul(g00, a0), cmul(g01, p0));
                a1 = cadd(cmul(g00, a1), cmul(g01, p1));
            }
        }
        // CNOT ring: composed permutation gather
        const int r = (l % (WIRES - 1)) + 1;
        buf[pb][t] = make_float4(a0.x, a0.y, a1.x, a1.y);
        __syncthreads();
        int p0i = t, p1i = t + 512;
#pragma unroll
        for (int w = WIRES - 1; w >= 0; w--) {
            const int cm = 1 << (9 - w);
            const int tm = 1 << (9 - ((w + r) % WIRES));
            if (p0i & cm) p0i ^= tm;
            if (p1i & cm) p1i ^= tm;
        }
        float4 q0 = buf[pb][p0i & 511];
        a0 = (p0i < 512) ? make_float2(q0.x, q0.y) : make_float2(q0.z, q0.w);
        float4 q1 = buf[pb][p1i & 511];
        a1 = (p1i < 512) ? make_float2(q1.x, q1.y) : make_float2(q1.z, q1.w);
        pb ^= 1;
    }
    // store B'[k=col][n=2j|2j+1] = (re, im), j = t / t+512; keep j < NBIG/2
    __half2* brow = (__half2*)(g_Bb + (size_t)col * NBIG);
    brow[t] = __floats2half2_rn(a0.x, a0.y);
    if (t < NBIG / 2 - 512)
        brow[t + 512] = __floats2half2_rn(a1.x, a1.y);
}

// ---------------- kernel 4: mma.sync fp16 GEMM + epilogue ----------------
// BM=128, BN=128, BK=64, 3-stage cp.async, 8 warps (2 M x 4 N), warp tile 64x32.
// A smem: [128 rows][128B] swizzled; B smem: [64 k-rows][256B] swizzled.
#define STAGE_BYTES 32768
#define GEMM_SMEM   (3 * STAGE_BYTES)   // 98304

__device__ __forceinline__ void load_tile(uint32_t sbase, int stage, int kt,
                                          const __half* gA,
                                          const __half* gB, int tid) {
    const uint32_t aS = sbase + stage * STAGE_BYTES;
    const uint32_t bS = aS + 16384;
    // A: 128 rows x 8 chunks(16B)
    {
        const int r0 = tid >> 3;
        const int c  = tid & 7;
        const uint32_t cx = (uint32_t)(c * 16);
#pragma unroll
        for (int p = 0; p < 4; p++) {
            const int row = p * 32 + r0;
            const uint32_t off = (uint32_t)(row * 128) + (cx ^ ((row & 7) * 16));
            cp_async16(aS + off, gA + (size_t)row * KBIG + (size_t)kt * BKT + c * 8);
        }
    }
    // B: 64 k-rows x 16 chunks(16B); thread: row = tid>>2, chunks (tid&3)*4 + q
    {
        const int r = tid >> 2;
        const int cq = (tid & 3) * 4;
        const __half* gsrc = gB + (size_t)(kt * BKT + r) * NBIG + cq * 8;
        const uint32_t rbase = bS + (uint32_t)(r * 256);
        const uint32_t rs = (uint32_t)((r & 7) * 16);
#pragma unroll
        for (int q = 0; q < 4; q++) {
            const uint32_t off = ((uint32_t)((cq + q) * 16)) ^ rs;
            cp_async16(rbase + off, gsrc + q * 8);
        }
    }
}

__global__ __launch_bounds__(256, 2) void k_gemm(float* __restrict__ out) {
    extern __shared__ char smem[];
    const uint32_t sbase = smem_u32(smem);
    const int tid = threadIdx.x;
    const int wid = tid >> 5, lane = tid & 31;
    const int wm = wid & 1, wn = wid >> 1;      // 2 x 4 warp grid
    const int m0 = blockIdx.x * 128;
    const int n0 = blockIdx.y * 128;

    const __half* gA = g_As + (size_t)m0 * KBIG;
    const __half* gB = g_Bb + n0;               // column offset into [k][n]

    float acc[4][4][4];
#pragma unroll
    for (int i = 0; i < 4; i++)
#pragma unroll
        for (int j = 0; j < 4; j++)
#pragma unroll
            for (int q = 0; q < 4; q++) acc[i][j][q] = 0.f;

    load_tile(sbase, 0, 0, gA, gB, tid); CP_COMMIT();
    load_tile(sbase, 1, 1, gA, gB, tid); CP_COMMIT();

    // A ldmatrix lane offsets (unchanged)
    const int a_row = wm * 64 + (lane & 7) + ((lane >> 3) & 1) * 8;
    const uint32_t a_kx = ((lane >> 4) & 1) * 16;
    // B ldmatrix.trans lane offsets: k-row within 16-group + n-chunk
    const int b_kr = (lane & 7) + ((lane >> 3) & 1) * 8;
    const int b_ch = wn * 4 + ((lane >> 4) & 1);

    int stage = 0;
    for (int kt = 0; kt < NKT; kt++) {
        if (kt + 2 < NKT) load_tile(sbase, (stage + 2) % 3, kt + 2, gA, gB, tid);
        CP_COMMIT();
        CP_WAIT2();
        __syncthreads();

        const uint32_t aS = sbase + stage * STAGE_BYTES;
        const uint32_t bS = aS + 16384;
#pragma unroll
        for (int ks = 0; ks < 4; ks++) {
            uint32_t afr[4][4], bfr[2][4];
#pragma unroll
            for (int mf = 0; mf < 4; mf++) {
                const int row = a_row + mf * 16;
                const uint32_t kb = (uint32_t)(ks * 32) + a_kx;
                ldsm_x4(afr[mf], aS + (uint32_t)(row * 128) + (kb ^ ((row & 7) * 16)));
            }
#pragma unroll
            for (int nf2 = 0; nf2 < 2; nf2++) {
                const int krow = ks * 16 + b_kr;
                const int ch = b_ch + nf2 * 2;
                ldsm_x4_t(bfr[nf2], bS + (uint32_t)(krow * 256) +
                                    (((uint32_t)(ch * 16)) ^ ((krow & 7) * 16)));
            }
#pragma unroll
            for (int mf = 0; mf < 4; mf++)
#pragma unroll
                for (int nf = 0; nf < 4; nf++)
                    mma16816(acc[mf][nf], afr[mf], &bfr[nf >> 1][(nf & 1) * 2]);
        }
        __syncthreads();
        stage = (stage + 1) % 3;
    }

    // epilogue: (c0,c1) = (re,im) of pixel j; (c2,c3) = row+8
    const int jbase = (n0 >> 1) + wn * 16;
    const int rbase = m0 + wm * 64 + (lane >> 2);
    const int jq = lane & 3;
#pragma unroll
    for (int mf = 0; mf < 4; mf++) {
#pragma unroll
        for (int nf = 0; nf < 4; nf++) {
            const int j = jbase + nf * 4 + jq;
            if (j < PIX) {
                const float re0 = acc[mf][nf][0], im0 = acc[mf][nf][1];
                const float re1 = acc[mf][nf][2], im1 = acc[mf][nf][3];
                out[(size_t)(rbase + mf * 16) * PIX + j] =
                    fminf((re0 * re0 + im0 * im0) * (float)PIX, 1.0f);
                out[(size_t)(rbase + mf * 16 + 8) * PIX + j] =
                    fminf((re1 * re1 + im1 * im1) * (float)PIX, 1.0f);
            }
        }
    }
}

// ---------------- launch ----------------
extern "C" void kernel_launch(void* const* d_in, const int* in_sizes, int n_in,
                              void* d_out, int out_size) {
    const float* x  = (const float*)d_in[0];
    const float* W  = (const float*)d_in[1];
    const float* b  = (const float*)d_in[2];
    const float* qw = (const float*)d_in[3];
    float* out = (float*)d_out;

    cudaFuncSetAttribute(k_gemm, cudaFuncAttributeMaxDynamicSharedMemorySize, GEMM_SMEM);

    k_gates<<<1, 256>>>(qw);                 // launch 1
    k_angA<<<BATCH / 8, 256>>>(x, W, b);     // launch 2
    k_buildU<<<DIM, 512>>>();                // launch 3
    dim3 gg(BATCH / 128, NBIG / 128);        // 64 x 13
    k_gemm<<<gg, 256, GEMM_SMEM>>>(out);     // launch 4  (ncu profile slot)
}